// round 3
// baseline (speedup 1.0000x reference)
#include <cuda_runtime.h>

// Problem constants
#define D_   1024
#define H_   16
#define HD_  64
#define B_   2
#define L_   2048
#define BL_  (B_ * L_)   // 4096

// ---------------- scratch (no allocations allowed -> __device__ globals) ----
__device__ float g_Q[(size_t)BL_ * D_];
__device__ float g_K[(size_t)BL_ * D_];
__device__ float g_V[(size_t)BL_ * D_];
__device__ float g_O[(size_t)BL_ * D_];

// ---------------- GEMM: C[m][n] = sum_k A[m][k] * W[n][k] + bias[n] --------
// A: [M, K] row-major, W: [N, K] row-major (i.e. X @ W^T), C: [M, N]
#define BM 128
#define BN 128
#define BKK 16

__global__ __launch_bounds__(256) void gemm_bias_kernel(
    const float* __restrict__ A, const float* __restrict__ W,
    const float* __restrict__ bias, float* __restrict__ C,
    int M, int N, int K)
{
    __shared__ __align__(16) float As[BKK][BM + 4];
    __shared__ __align__(16) float Bs[BKK][BN + 4];

    const int bm = blockIdx.y * BM;
    const int bn = blockIdx.x * BN;
    const int tid = threadIdx.x;
    const int tm = (tid >> 4) << 3;   // 0..120
    const int tn = (tid & 15) << 3;   // 0..120

    float acc[8][8];
#pragma unroll
    for (int i = 0; i < 8; i++)
#pragma unroll
        for (int j = 0; j < 8; j++) acc[i][j] = 0.f;

    for (int k0 = 0; k0 < K; k0 += BKK) {
        // Stage A tile (BM x BKK) and W tile (BN x BKK), transposed into smem.
        // 512 float4 loads per tile, 256 threads -> 2 each.
#pragma unroll
        for (int r = 0; r < 2; r++) {
            int f   = tid + r * 256;        // float4 id in [0, 512)
            int row = f >> 2;               // 0..127
            int c4  = (f & 3) << 2;         // 0,4,8,12
            float4 va = *(const float4*)&A[(size_t)(bm + row) * K + k0 + c4];
            As[c4 + 0][row] = va.x; As[c4 + 1][row] = va.y;
            As[c4 + 2][row] = va.z; As[c4 + 3][row] = va.w;
            float4 vb = *(const float4*)&W[(size_t)(bn + row) * K + k0 + c4];
            Bs[c4 + 0][row] = vb.x; Bs[c4 + 1][row] = vb.y;
            Bs[c4 + 2][row] = vb.z; Bs[c4 + 3][row] = vb.w;
        }
        __syncthreads();

#pragma unroll
        for (int k = 0; k < BKK; k++) {
            float a[8], b[8];
            *(float4*)&a[0] = *(const float4*)&As[k][tm];
            *(float4*)&a[4] = *(const float4*)&As[k][tm + 4];
            *(float4*)&b[0] = *(const float4*)&Bs[k][tn];
            *(float4*)&b[4] = *(const float4*)&Bs[k][tn + 4];
#pragma unroll
            for (int i = 0; i < 8; i++)
#pragma unroll
                for (int j = 0; j < 8; j++)
                    acc[i][j] += a[i] * b[j];
        }
        __syncthreads();
    }

#pragma unroll
    for (int i = 0; i < 8; i++) {
        size_t row = (size_t)(bm + tm + i) * N + bn + tn;
#pragma unroll
        for (int j = 0; j < 8; j += 4) {
            float4 o;
            o.x = acc[i][j + 0] + bias[bn + tn + j + 0];
            o.y = acc[i][j + 1] + bias[bn + tn + j + 1];
            o.z = acc[i][j + 2] + bias[bn + tn + j + 2];
            o.w = acc[i][j + 3] + bias[bn + tn + j + 3];
            *(float4*)&C[row + j] = o;
        }
    }
}

// ---------------- RoPE (in-place on Q and K scratch) -----------------------
// freqs: [L, HD] with freqs[l, d] == freqs[l, d+32] for d < 32.
__global__ __launch_bounds__(256) void rope_kernel(
    float* __restrict__ Q, float* __restrict__ K, const float* __restrict__ freqs)
{
    const int total = BL_ * H_ * (HD_ / 2);
    int idx = blockIdx.x * blockDim.x + threadIdx.x;
    if (idx >= total) return;
    int d  = idx & 31;
    int t  = idx >> 5;
    int h  = t & (H_ - 1);
    int bl = t >> 4;            // H_=16
    int l  = bl & (L_ - 1);

    float f = freqs[l * HD_ + d];
    float s, c;
    sincosf(f, &s, &c);

    size_t base = (size_t)bl * D_ + h * HD_;
    float q1 = Q[base + d], q2 = Q[base + d + 32];
    Q[base + d]      = q1 * c - q2 * s;
    Q[base + d + 32] = q2 * c + q1 * s;
    float k1 = K[base + d], k2 = K[base + d + 32];
    K[base + d]      = k1 * c - k2 * s;
    K[base + d + 32] = k2 * c + k1 * s;
}

// ---------------- Attention (flash-style, fp32) ----------------------------
// Block: 128 threads. 16 query rows, 8 lanes per row (each lane: 8 head dims).
#define QT 16
#define KT 64

__global__ __launch_bounds__(128) void attn_kernel(
    const float* __restrict__ Q, const float* __restrict__ K,
    const float* __restrict__ V, float* __restrict__ O)
{
    __shared__ __align__(16) float Ks[KT][HD_];
    __shared__ __align__(16) float Vs[KT][HD_];

    const int tid = threadIdx.x;
    const int row = tid >> 3;        // 0..15
    const int sub = tid & 7;         // 0..7
    const int b = blockIdx.z, h = blockIdx.y;
    const int qi = blockIdx.x * QT + row;

    const size_t qoff = (size_t)(b * L_ + qi) * D_ + h * HD_ + sub * 8;
    float q[8];
    *(float4*)&q[0] = *(const float4*)&Q[qoff];
    *(float4*)&q[4] = *(const float4*)&Q[qoff + 4];

    float acc[8];
#pragma unroll
    for (int i = 0; i < 8; i++) acc[i] = 0.f;
    float m = -INFINITY, lsum = 0.f;
    const float scale = 0.125f;   // 1/sqrt(64)

    for (int t0 = 0; t0 < L_; t0 += KT) {
        // Stage KT keys + values: 2*KT*64 floats = 2048 float4 / 128 threads
#pragma unroll
        for (int r = 0; r < KT / 8; r++) {
            int f  = tid + r * 128;          // [0, KT*16)
            int kj = f >> 4;                 // 0..KT-1
            int c4 = (f & 15) << 2;          // 0..60
            size_t goff = (size_t)(b * L_ + t0 + kj) * D_ + h * HD_ + c4;
            *(float4*)&Ks[kj][c4] = *(const float4*)&K[goff];
            *(float4*)&Vs[kj][c4] = *(const float4*)&V[goff];
        }
        __syncthreads();

#pragma unroll 4
        for (int j = 0; j < KT; j++) {
            float kr[8];
            *(float4*)&kr[0] = *(const float4*)&Ks[j][sub * 8];
            *(float4*)&kr[4] = *(const float4*)&Ks[j][sub * 8 + 4];
            float p = 0.f;
#pragma unroll
            for (int i = 0; i < 8; i++) p += q[i] * kr[i];
            // reduce across the 8 lanes of this row (lanes stay in-group)
            p += __shfl_xor_sync(0xffffffffu, p, 1);
            p += __shfl_xor_sync(0xffffffffu, p, 2);
            p += __shfl_xor_sync(0xffffffffu, p, 4);
            float s = p * scale;
            if (s > m) {
                float corr = __expf(m - s);
                lsum *= corr;
#pragma unroll
                for (int i = 0; i < 8; i++) acc[i] *= corr;
                m = s;
            }
            float pe = __expf(s - m);
            lsum += pe;
            float vr[8];
            *(float4*)&vr[0] = *(const float4*)&Vs[j][sub * 8];
            *(float4*)&vr[4] = *(const float4*)&Vs[j][sub * 8 + 4];
#pragma unroll
            for (int i = 0; i < 8; i++) acc[i] += pe * vr[i];
        }
        __syncthreads();
    }

    float inv = 1.f / lsum;
    size_t ooff = (size_t)(b * L_ + qi) * D_ + h * HD_ + sub * 8;
    float4 o1, o2;
    o1.x = acc[0] * inv; o1.y = acc[1] * inv; o1.z = acc[2] * inv; o1.w = acc[3] * inv;
    o2.x = acc[4] * inv; o2.y = acc[5] * inv; o2.z = acc[6] * inv; o2.w = acc[7] * inv;
    *(float4*)&O[ooff]     = o1;
    *(float4*)&O[ooff + 4] = o2;
}

// ---------------- launch ---------------------------------------------------
extern "C" void kernel_launch(void* const* d_in, const int* in_sizes, int n_in,
                              void* d_out, int out_size)
{
    (void)in_sizes; (void)n_in; (void)out_size;
    const float* q  = (const float*)d_in[0];
    const float* k  = (const float*)d_in[1];
    const float* v  = (const float*)d_in[2];
    const float* fr = (const float*)d_in[3];
    const float* Wq = (const float*)d_in[4];
    const float* bq = (const float*)d_in[5];
    const float* Wk = (const float*)d_in[6];
    const float* bk = (const float*)d_in[7];
    const float* Wv = (const float*)d_in[8];
    const float* bv = (const float*)d_in[9];
    const float* Wo = (const float*)d_in[10];
    const float* bo = (const float*)d_in[11];
    float* out = (float*)d_out;

    float *Qs, *Ks, *Vs, *Os;
    cudaGetSymbolAddress((void**)&Qs, g_Q);
    cudaGetSymbolAddress((void**)&Ks, g_K);
    cudaGetSymbolAddress((void**)&Vs, g_V);
    cudaGetSymbolAddress((void**)&Os, g_O);

    dim3 ggrid(D_ / BN, BL_ / BM);   // (8, 32)
    gemm_bias_kernel<<<ggrid, 256>>>(q, Wq, bq, Qs, BL_, D_, D_);
    gemm_bias_kernel<<<ggrid, 256>>>(k, Wk, bk, Ks, BL_, D_, D_);
    gemm_bias_kernel<<<ggrid, 256>>>(v, Wv, bv, Vs, BL_, D_, D_);

    int rope_total = BL_ * H_ * (HD_ / 2);
    rope_kernel<<<(rope_total + 255) / 256, 256>>>(Qs, Ks, fr);

    dim3 agrid(L_ / QT, H_, B_);     // (128, 16, 2)
    attn_kernel<<<agrid, 128>>>(Qs, Ks, Vs, Os);

    gemm_bias_kernel<<<ggrid, 256>>>(Os, Wo, bo, out, BL_, D_, D_);
}

// round 5
// speedup vs baseline: 1.0817x; 1.0817x over previous
#include <cuda_runtime.h>
#include <cuda_bf16.h>
#include <cstdint>

// Problem constants
#define D_   1024
#define H_   16
#define HD_  64
#define B_   2
#define L_   2048
#define BL_  (B_ * L_)   // 4096
#define K3_  (3 * D_)    // 3072 (K-tripled split-bf16)

// ---------------- scratch (no allocations allowed -> __device__ globals) ----
__device__ float g_Q[(size_t)BL_ * D_];
__device__ float g_K[(size_t)BL_ * D_];
__device__ float g_V[(size_t)BL_ * D_];
__device__ float g_O[(size_t)BL_ * D_];
__device__ __nv_bfloat16 g_X3[(size_t)BL_ * K3_];   // activations, K-tripled
__device__ __nv_bfloat16 g_W3[(size_t)D_ * K3_];    // weights, K-tripled

// ---------------- PTX helpers (sm_80-era ops only: safe on plain sm_103) ---
__device__ __forceinline__ uint32_t smem_u32(const void* p) {
    uint32_t a;
    asm("{ .reg .u64 t; cvta.to.shared.u64 t, %1; cvt.u32.u64 %0, t; }"
        : "=r"(a) : "l"(p));
    return a;
}
__device__ __forceinline__ void ldm_x4(uint32_t* r, uint32_t addr) {
    asm volatile("ldmatrix.sync.aligned.m8n8.x4.shared.b16 {%0,%1,%2,%3}, [%4];"
                 : "=r"(r[0]), "=r"(r[1]), "=r"(r[2]), "=r"(r[3]) : "r"(addr));
}
__device__ __forceinline__ void mma_bf16(float* c, const uint32_t* a, const uint32_t* b) {
    asm volatile("mma.sync.aligned.m16n8k16.row.col.f32.bf16.bf16.f32 "
                 "{%0,%1,%2,%3}, {%4,%5,%6,%7}, {%8,%9}, {%0,%1,%2,%3};"
                 : "+f"(c[0]), "+f"(c[1]), "+f"(c[2]), "+f"(c[3])
                 : "r"(a[0]), "r"(a[1]), "r"(a[2]), "r"(a[3]), "r"(b[0]), "r"(b[1]));
}

// ---------------- split-bf16 K-tripling conversion -------------------------
// mode 0 (activations): (hi, hi, lo)   mode 1 (weights): (hi, lo, hi)
__global__ __launch_bounds__(256) void conv3_kernel(
    const float* __restrict__ in, __nv_bfloat16* __restrict__ out, int total8, int mode)
{
    int idx = blockIdx.x * blockDim.x + threadIdx.x;
    if (idx >= total8) return;
    float4 v0 = ((const float4*)in)[idx * 2];
    float4 v1 = ((const float4*)in)[idx * 2 + 1];
    float a[8] = {v0.x, v0.y, v0.z, v0.w, v1.x, v1.y, v1.z, v1.w};
    __align__(16) __nv_bfloat16 o[24];
#pragma unroll
    for (int i = 0; i < 8; i++) {
        __nv_bfloat16 hi = __float2bfloat16(a[i]);
        __nv_bfloat16 lo = __float2bfloat16(a[i] - __bfloat162float(hi));
        if (mode == 0) { o[3*i] = hi; o[3*i+1] = hi; o[3*i+2] = lo; }
        else           { o[3*i] = hi; o[3*i+1] = lo; o[3*i+2] = hi; }
    }
    uint4* dst = (uint4*)(out + (size_t)idx * 24);
    const uint4* src = (const uint4*)o;
    dst[0] = src[0]; dst[1] = src[1]; dst[2] = src[2];
}

// ---------------- mma.sync GEMM: C[m][n] = sum_k A3[m][k]*W3[n][k] + bias --
// A3: [M, K3] bf16 row-major, W3: [N, K3] bf16 row-major (= B col-major in k)
#define BMt 128
#define BNt 128
#define KS  32
#define AROW 40                 // 32 + 8 pad halves: 80B rows, ldmatrix conflict-free
#define NCH (K3_ / KS)          // 96

__global__ __launch_bounds__(256) void gemm_mma_kernel(
    const __nv_bfloat16* __restrict__ A3, const __nv_bfloat16* __restrict__ W3,
    const float* __restrict__ bias, float* __restrict__ C, int N)
{
    __shared__ __align__(16) __nv_bfloat16 As[2][BMt][AROW];
    __shared__ __align__(16) __nv_bfloat16 Bs[2][BNt][AROW];

    const int tid  = threadIdx.x;
    const int wid  = tid >> 5;
    const int lane = tid & 31;
    const int bm = blockIdx.y * BMt;
    const int bn = blockIdx.x * BNt;
    const int wm = (wid >> 2) * 64;   // warp M offset: 0 / 64
    const int wn = (wid & 3) * 32;    // warp N offset: 0..96

    // staging geometry: 512 uint4 per operand tile, 256 threads -> 2 each
    const int r0row = tid >> 2,        r0c = tid & 3;
    const int r1row = (tid + 256) >> 2, r1c = (tid + 256) & 3;

    float acc[4][4][4];
#pragma unroll
    for (int mi = 0; mi < 4; mi++)
#pragma unroll
        for (int nj = 0; nj < 4; nj++)
#pragma unroll
            for (int e = 0; e < 4; e++) acc[mi][nj][e] = 0.f;

    uint4 pa0, pa1, pb0, pb1;
    // load chunk 0
    pa0 = *(const uint4*)&A3[(size_t)(bm + r0row) * K3_ + r0c * 8];
    pa1 = *(const uint4*)&A3[(size_t)(bm + r1row) * K3_ + r1c * 8];
    pb0 = *(const uint4*)&W3[(size_t)(bn + r0row) * K3_ + r0c * 8];
    pb1 = *(const uint4*)&W3[(size_t)(bn + r1row) * K3_ + r1c * 8];
    *(uint4*)&As[0][r0row][r0c * 8] = pa0;
    *(uint4*)&As[0][r1row][r1c * 8] = pa1;
    *(uint4*)&Bs[0][r0row][r0c * 8] = pb0;
    *(uint4*)&Bs[0][r1row][r1c * 8] = pb1;
    __syncthreads();

    // ldmatrix lane addressing (in halves)
    const int lrowA = wm + (lane & 15);              // + mi*16
    const int koffA = (lane >> 4) << 3;              // 0 / 8, + kk*16
    const int lrowB = wn + (lane & 7) + ((lane >> 4) << 3);  // + nj2*16
    const int koffB = ((lane >> 3) & 1) << 3;        // 0 / 8, + kk*16

    for (int ch = 0; ch < NCH; ch++) {
        const int p = ch & 1;
        if (ch + 1 < NCH) {
            const int k0 = (ch + 1) * KS;
            pa0 = *(const uint4*)&A3[(size_t)(bm + r0row) * K3_ + k0 + r0c * 8];
            pa1 = *(const uint4*)&A3[(size_t)(bm + r1row) * K3_ + k0 + r1c * 8];
            pb0 = *(const uint4*)&W3[(size_t)(bn + r0row) * K3_ + k0 + r0c * 8];
            pb1 = *(const uint4*)&W3[(size_t)(bn + r1row) * K3_ + k0 + r1c * 8];
        }

        const uint32_t a_base = smem_u32(&As[p][0][0]);
        const uint32_t b_base = smem_u32(&Bs[p][0][0]);
#pragma unroll
        for (int kk = 0; kk < 2; kk++) {
            uint32_t afr[4][4], bfr[2][4];
#pragma unroll
            for (int mi = 0; mi < 4; mi++)
                ldm_x4(afr[mi], a_base + (uint32_t)(((lrowA + mi * 16) * AROW) + kk * 16 + koffA) * 2);
#pragma unroll
            for (int nj2 = 0; nj2 < 2; nj2++)
                ldm_x4(bfr[nj2], b_base + (uint32_t)(((lrowB + nj2 * 16) * AROW) + kk * 16 + koffB) * 2);
#pragma unroll
            for (int mi = 0; mi < 4; mi++)
#pragma unroll
                for (int nj = 0; nj < 4; nj++)
                    mma_bf16(acc[mi][nj], afr[mi], &bfr[nj >> 1][(nj & 1) * 2]);
        }

        if (ch + 1 < NCH) {
            const int q = p ^ 1;
            *(uint4*)&As[q][r0row][r0c * 8] = pa0;
            *(uint4*)&As[q][r1row][r1c * 8] = pa1;
            *(uint4*)&Bs[q][r0row][r0c * 8] = pb0;
            *(uint4*)&Bs[q][r1row][r1c * 8] = pb1;
        }
        __syncthreads();
    }

    // epilogue: c-fragment m16n8 layout
    const int crow = wm + (lane >> 2);
    const int ccol = wn + (lane & 3) * 2;
#pragma unroll
    for (int mi = 0; mi < 4; mi++) {
#pragma unroll
        for (int nj = 0; nj < 4; nj++) {
            const int m0 = bm + crow + mi * 16;
            const int n0 = bn + ccol + nj * 8;
            const float b0v = __ldg(&bias[n0]), b1v = __ldg(&bias[n0 + 1]);
            float2 v0 = {acc[mi][nj][0] + b0v, acc[mi][nj][1] + b1v};
            float2 v1 = {acc[mi][nj][2] + b0v, acc[mi][nj][3] + b1v};
            *(float2*)&C[(size_t)m0 * N + n0]       = v0;
            *(float2*)&C[(size_t)(m0 + 8) * N + n0] = v1;
        }
    }
}

// ---------------- RoPE (in-place on Q and K scratch) -----------------------
__global__ __launch_bounds__(256) void rope_kernel(
    float* __restrict__ Q, float* __restrict__ K, const float* __restrict__ freqs)
{
    const int total = BL_ * H_ * (HD_ / 2);
    int idx = blockIdx.x * blockDim.x + threadIdx.x;
    if (idx >= total) return;
    int d  = idx & 31;
    int t  = idx >> 5;
    int h  = t & (H_ - 1);
    int bl = t >> 4;
    int l  = bl & (L_ - 1);

    float f = freqs[l * HD_ + d];
    float s, c;
    sincosf(f, &s, &c);

    size_t base = (size_t)bl * D_ + h * HD_;
    float q1 = Q[base + d], q2 = Q[base + d + 32];
    Q[base + d]      = q1 * c - q2 * s;
    Q[base + d + 32] = q2 * c + q1 * s;
    float k1 = K[base + d], k2 = K[base + d + 32];
    K[base + d]      = k1 * c - k2 * s;
    K[base + d + 32] = k2 * c + k1 * s;
}

// ---------------- Attention (flash-style, fp32) ----------------------------
#define QT 16
#define KT 64

__global__ __launch_bounds__(128) void attn_kernel(
    const float* __restrict__ Q, const float* __restrict__ K,
    const float* __restrict__ V, float* __restrict__ O)
{
    __shared__ __align__(16) float Ks[KT][HD_];
    __shared__ __align__(16) float Vs[KT][HD_];

    const int tid = threadIdx.x;
    const int row = tid >> 3;
    const int sub = tid & 7;
    const int b = blockIdx.z, h = blockIdx.y;
    const int qi = blockIdx.x * QT + row;

    const size_t qoff = (size_t)(b * L_ + qi) * D_ + h * HD_ + sub * 8;
    float q[8];
    *(float4*)&q[0] = *(const float4*)&Q[qoff];
    *(float4*)&q[4] = *(const float4*)&Q[qoff + 4];

    float acc[8];
#pragma unroll
    for (int i = 0; i < 8; i++) acc[i] = 0.f;
    float m = -INFINITY, lsum = 0.f;
    const float scale = 0.125f;

    for (int t0 = 0; t0 < L_; t0 += KT) {
#pragma unroll
        for (int r = 0; r < KT / 8; r++) {
            int f  = tid + r * 128;
            int kj = f >> 4;
            int c4 = (f & 15) << 2;
            size_t goff = (size_t)(b * L_ + t0 + kj) * D_ + h * HD_ + c4;
            *(float4*)&Ks[kj][c4] = *(const float4*)&K[goff];
            *(float4*)&Vs[kj][c4] = *(const float4*)&V[goff];
        }
        __syncthreads();

#pragma unroll 4
        for (int j = 0; j < KT; j++) {
            float kr[8];
            *(float4*)&kr[0] = *(const float4*)&Ks[j][sub * 8];
            *(float4*)&kr[4] = *(const float4*)&Ks[j][sub * 8 + 4];
            float p = 0.f;
#pragma unroll
            for (int i = 0; i < 8; i++) p += q[i] * kr[i];
            p += __shfl_xor_sync(0xffffffffu, p, 1);
            p += __shfl_xor_sync(0xffffffffu, p, 2);
            p += __shfl_xor_sync(0xffffffffu, p, 4);
            float s = p * scale;
            if (s > m) {
                float corr = __expf(m - s);
                lsum *= corr;
#pragma unroll
                for (int i = 0; i < 8; i++) acc[i] *= corr;
                m = s;
            }
            float pe = __expf(s - m);
            lsum += pe;
            float vr[8];
            *(float4*)&vr[0] = *(const float4*)&Vs[j][sub * 8];
            *(float4*)&vr[4] = *(const float4*)&Vs[j][sub * 8 + 4];
#pragma unroll
            for (int i = 0; i < 8; i++) acc[i] += pe * vr[i];
        }
        __syncthreads();
    }

    float inv = 1.f / lsum;
    size_t ooff = (size_t)(b * L_ + qi) * D_ + h * HD_ + sub * 8;
    float4 o1, o2;
    o1.x = acc[0] * inv; o1.y = acc[1] * inv; o1.z = acc[2] * inv; o1.w = acc[3] * inv;
    o2.x = acc[4] * inv; o2.y = acc[5] * inv; o2.z = acc[6] * inv; o2.w = acc[7] * inv;
    *(float4*)&O[ooff]     = o1;
    *(float4*)&O[ooff + 4] = o2;
}

// ---------------- launch ---------------------------------------------------
extern "C" void kernel_launch(void* const* d_in, const int* in_sizes, int n_in,
                              void* d_out, int out_size)
{
    (void)in_sizes; (void)n_in; (void)out_size;
    const float* q  = (const float*)d_in[0];
    const float* k  = (const float*)d_in[1];
    const float* v  = (const float*)d_in[2];
    const float* fr = (const float*)d_in[3];
    const float* Wq = (const float*)d_in[4];
    const float* bq = (const float*)d_in[5];
    const float* Wk = (const float*)d_in[6];
    const float* bk = (const float*)d_in[7];
    const float* Wv = (const float*)d_in[8];
    const float* bv = (const float*)d_in[9];
    const float* Wo = (const float*)d_in[10];
    const float* bo = (const float*)d_in[11];
    float* out = (float*)d_out;

    float *Qs, *Ks, *Vs, *Os;
    __nv_bfloat16 *X3, *W3;
    cudaGetSymbolAddress((void**)&Qs, g_Q);
    cudaGetSymbolAddress((void**)&Ks, g_K);
    cudaGetSymbolAddress((void**)&Vs, g_V);
    cudaGetSymbolAddress((void**)&Os, g_O);
    cudaGetSymbolAddress((void**)&X3, g_X3);
    cudaGetSymbolAddress((void**)&W3, g_W3);

    const int xt8 = BL_ * D_ / 8;
    const int wt8 = D_ * D_ / 8;
    dim3 ggrid(D_ / BNt, BL_ / BMt);   // (8, 32)

    conv3_kernel<<<(xt8 + 255) / 256, 256>>>(q, X3, xt8, 0);
    conv3_kernel<<<(wt8 + 255) / 256, 256>>>(Wq, W3, wt8, 1);
    gemm_mma_kernel<<<ggrid, 256>>>(X3, W3, bq, Qs, D_);

    conv3_kernel<<<(xt8 + 255) / 256, 256>>>(k, X3, xt8, 0);
    conv3_kernel<<<(wt8 + 255) / 256, 256>>>(Wk, W3, wt8, 1);
    gemm_mma_kernel<<<ggrid, 256>>>(X3, W3, bk, Ks, D_);

    conv3_kernel<<<(xt8 + 255) / 256, 256>>>(v, X3, xt8, 0);
    conv3_kernel<<<(wt8 + 255) / 256, 256>>>(Wv, W3, wt8, 1);
    gemm_mma_kernel<<<ggrid, 256>>>(X3, W3, bv, Vs, D_);

    int rope_total = BL_ * H_ * (HD_ / 2);
    rope_kernel<<<(rope_total + 255) / 256, 256>>>(Qs, Ks, fr);

    dim3 agrid(L_ / QT, H_, B_);
    attn_kernel<<<agrid, 128>>>(Qs, Ks, Vs, Os);

    conv3_kernel<<<(xt8 + 255) / 256, 256>>>(Os, X3, xt8, 0);
    conv3_kernel<<<(wt8 + 255) / 256, 256>>>(Wo, W3, wt8, 1);
    gemm_mma_kernel<<<ggrid, 256>>>(X3, W3, bo, out, D_);
}

// round 6
// speedup vs baseline: 6.2896x; 5.8148x over previous
#include <cuda_runtime.h>
#include <cuda_bf16.h>
#include <cstdint>

// Problem constants
#define D_   1024
#define H_   16
#define HD_  64
#define B_   2
#define L_   2048
#define BL_  (B_ * L_)   // 4096
#define K3_  (3 * D_)    // 3072 (K-tripled split-bf16 for projections)
#define BH_  (B_ * H_)   // 32
#define AD3  192         // tripled head dim

// ---------------- scratch (no allocations allowed -> __device__ globals) ----
__device__ float g_Q[(size_t)BL_ * D_];
__device__ float g_K[(size_t)BL_ * D_];
__device__ float g_V[(size_t)BL_ * D_];
__device__ float g_O[(size_t)BL_ * D_];
__device__ __nv_bfloat16 g_X3[(size_t)BL_ * K3_];          // activations, K-tripled
__device__ __nv_bfloat16 g_W3[(size_t)D_ * K3_];           // weights, K-tripled
__device__ __nv_bfloat16 g_Q3[(size_t)BH_ * L_ * AD3];     // rope+scale+split Q
__device__ __nv_bfloat16 g_K3[(size_t)BH_ * L_ * AD3];     // rope+split K
__device__ __nv_bfloat16 g_VTh[(size_t)BH_ * HD_ * L_];    // V^T hi
__device__ __nv_bfloat16 g_VTl[(size_t)BH_ * HD_ * L_];    // V^T lo

// ---------------- PTX helpers (sm_80-era ops: safe on plain sm_103) --------
__device__ __forceinline__ uint32_t smem_u32(const void* p) {
    uint32_t a;
    asm("{ .reg .u64 t; cvta.to.shared.u64 t, %1; cvt.u32.u64 %0, t; }"
        : "=r"(a) : "l"(p));
    return a;
}
__device__ __forceinline__ void ldm_x4(uint32_t* r, uint32_t addr) {
    asm volatile("ldmatrix.sync.aligned.m8n8.x4.shared.b16 {%0,%1,%2,%3}, [%4];"
                 : "=r"(r[0]), "=r"(r[1]), "=r"(r[2]), "=r"(r[3]) : "r"(addr));
}
__device__ __forceinline__ void mma_bf16(float* c, const uint32_t* a, const uint32_t* b) {
    asm volatile("mma.sync.aligned.m16n8k16.row.col.f32.bf16.bf16.f32 "
                 "{%0,%1,%2,%3}, {%4,%5,%6,%7}, {%8,%9}, {%0,%1,%2,%3};"
                 : "+f"(c[0]), "+f"(c[1]), "+f"(c[2]), "+f"(c[3])
                 : "r"(a[0]), "r"(a[1]), "r"(a[2]), "r"(a[3]), "r"(b[0]), "r"(b[1]));
}
__device__ __forceinline__ uint32_t pack_bf2(float x, float y) {
    __nv_bfloat162 t = __float22bfloat162_rn(make_float2(x, y));
    return *(uint32_t*)&t;
}
__device__ __forceinline__ uint32_t pack_bf2_lo(float x, float y, uint32_t hp) {
    __nv_bfloat162 h = *(__nv_bfloat162*)&hp;
    return pack_bf2(x - __bfloat162float(h.x), y - __bfloat162float(h.y));
}

// ---------------- split-bf16 K-tripling conversion (projections) -----------
// mode 0 (activations): (hi, hi, lo)   mode 1 (weights): (hi, lo, hi)
__global__ __launch_bounds__(256) void conv3_kernel(
    const float* __restrict__ in, __nv_bfloat16* __restrict__ out, int total8, int mode)
{
    int idx = blockIdx.x * blockDim.x + threadIdx.x;
    if (idx >= total8) return;
    float4 v0 = ((const float4*)in)[idx * 2];
    float4 v1 = ((const float4*)in)[idx * 2 + 1];
    float a[8] = {v0.x, v0.y, v0.z, v0.w, v1.x, v1.y, v1.z, v1.w};
    __align__(16) __nv_bfloat16 o[24];
#pragma unroll
    for (int i = 0; i < 8; i++) {
        __nv_bfloat16 hi = __float2bfloat16(a[i]);
        __nv_bfloat16 lo = __float2bfloat16(a[i] - __bfloat162float(hi));
        if (mode == 0) { o[3*i] = hi; o[3*i+1] = hi; o[3*i+2] = lo; }
        else           { o[3*i] = hi; o[3*i+1] = lo; o[3*i+2] = hi; }
    }
    uint4* dst = (uint4*)(out + (size_t)idx * 24);
    const uint4* src = (const uint4*)o;
    dst[0] = src[0]; dst[1] = src[1]; dst[2] = src[2];
}

// ---------------- mma.sync GEMM (unchanged from R5, verified) --------------
#define BMt 128
#define BNt 128
#define KS  32
#define AROW 40
#define NCH (K3_ / KS)          // 96

__global__ __launch_bounds__(256) void gemm_mma_kernel(
    const __nv_bfloat16* __restrict__ A3, const __nv_bfloat16* __restrict__ W3,
    const float* __restrict__ bias, float* __restrict__ C, int N)
{
    __shared__ __align__(16) __nv_bfloat16 As[2][BMt][AROW];
    __shared__ __align__(16) __nv_bfloat16 Bs[2][BNt][AROW];

    const int tid  = threadIdx.x;
    const int wid  = tid >> 5;
    const int lane = tid & 31;
    const int bm = blockIdx.y * BMt;
    const int bn = blockIdx.x * BNt;
    const int wm = (wid >> 2) * 64;
    const int wn = (wid & 3) * 32;

    const int r0row = tid >> 2,         r0c = tid & 3;
    const int r1row = (tid + 256) >> 2, r1c = (tid + 256) & 3;

    float acc[4][4][4];
#pragma unroll
    for (int mi = 0; mi < 4; mi++)
#pragma unroll
        for (int nj = 0; nj < 4; nj++)
#pragma unroll
            for (int e = 0; e < 4; e++) acc[mi][nj][e] = 0.f;

    uint4 pa0, pa1, pb0, pb1;
    pa0 = *(const uint4*)&A3[(size_t)(bm + r0row) * K3_ + r0c * 8];
    pa1 = *(const uint4*)&A3[(size_t)(bm + r1row) * K3_ + r1c * 8];
    pb0 = *(const uint4*)&W3[(size_t)(bn + r0row) * K3_ + r0c * 8];
    pb1 = *(const uint4*)&W3[(size_t)(bn + r1row) * K3_ + r1c * 8];
    *(uint4*)&As[0][r0row][r0c * 8] = pa0;
    *(uint4*)&As[0][r1row][r1c * 8] = pa1;
    *(uint4*)&Bs[0][r0row][r0c * 8] = pb0;
    *(uint4*)&Bs[0][r1row][r1c * 8] = pb1;
    __syncthreads();

    const int lrowA = wm + (lane & 15);
    const int koffA = (lane >> 4) << 3;
    const int lrowB = wn + (lane & 7) + ((lane >> 4) << 3);
    const int koffB = ((lane >> 3) & 1) << 3;

    for (int ch = 0; ch < NCH; ch++) {
        const int p = ch & 1;
        if (ch + 1 < NCH) {
            const int k0 = (ch + 1) * KS;
            pa0 = *(const uint4*)&A3[(size_t)(bm + r0row) * K3_ + k0 + r0c * 8];
            pa1 = *(const uint4*)&A3[(size_t)(bm + r1row) * K3_ + k0 + r1c * 8];
            pb0 = *(const uint4*)&W3[(size_t)(bn + r0row) * K3_ + k0 + r0c * 8];
            pb1 = *(const uint4*)&W3[(size_t)(bn + r1row) * K3_ + k0 + r1c * 8];
        }
        const uint32_t a_base = smem_u32(&As[p][0][0]);
        const uint32_t b_base = smem_u32(&Bs[p][0][0]);
#pragma unroll
        for (int kk = 0; kk < 2; kk++) {
            uint32_t afr[4][4], bfr[2][4];
#pragma unroll
            for (int mi = 0; mi < 4; mi++)
                ldm_x4(afr[mi], a_base + (uint32_t)(((lrowA + mi * 16) * AROW) + kk * 16 + koffA) * 2);
#pragma unroll
            for (int nj2 = 0; nj2 < 2; nj2++)
                ldm_x4(bfr[nj2], b_base + (uint32_t)(((lrowB + nj2 * 16) * AROW) + kk * 16 + koffB) * 2);
#pragma unroll
            for (int mi = 0; mi < 4; mi++)
#pragma unroll
                for (int nj = 0; nj < 4; nj++)
                    mma_bf16(acc[mi][nj], afr[mi], &bfr[nj >> 1][(nj & 1) * 2]);
        }
        if (ch + 1 < NCH) {
            const int q = p ^ 1;
            *(uint4*)&As[q][r0row][r0c * 8] = pa0;
            *(uint4*)&As[q][r1row][r1c * 8] = pa1;
            *(uint4*)&Bs[q][r0row][r0c * 8] = pb0;
            *(uint4*)&Bs[q][r1row][r1c * 8] = pb1;
        }
        __syncthreads();
    }

    const int crow = wm + (lane >> 2);
    const int ccol = wn + (lane & 3) * 2;
#pragma unroll
    for (int mi = 0; mi < 4; mi++) {
#pragma unroll
        for (int nj = 0; nj < 4; nj++) {
            const int m0 = bm + crow + mi * 16;
            const int n0 = bn + ccol + nj * 8;
            const float b0v = __ldg(&bias[n0]), b1v = __ldg(&bias[n0 + 1]);
            float2 v0 = {acc[mi][nj][0] + b0v, acc[mi][nj][1] + b1v};
            float2 v1 = {acc[mi][nj][2] + b0v, acc[mi][nj][3] + b1v};
            *(float2*)&C[(size_t)m0 * N + n0]       = v0;
            *(float2*)&C[(size_t)(m0 + 8) * N + n0] = v1;
        }
    }
}

// ---------------- RoPE + triple-split into per-head layout -----------------
// Q: pattern (hi,hi,lo), pre-scaled by 0.125 (exact).  K: pattern (hi,lo,hi).
__global__ __launch_bounds__(256) void rope_split_kernel(
    const float* __restrict__ Q, const float* __restrict__ K,
    const float* __restrict__ freqs,
    __nv_bfloat16* __restrict__ Q3, __nv_bfloat16* __restrict__ K3)
{
    int idx = blockIdx.x * blockDim.x + threadIdx.x;   // BL_*H_*32 total
    int d  = idx & 31;
    int h  = (idx >> 5) & 15;
    int bl = idx >> 9;
    if (bl >= BL_) return;
    int l = bl & (L_ - 1);
    int b = bl >> 11;
    int bh = b * H_ + h;

    float f = freqs[l * HD_ + d];
    float s, c;
    sincosf(f, &s, &c);

    size_t base = (size_t)bl * D_ + h * HD_;
    float q1 = Q[base + d], q2 = Q[base + d + 32];
    float rq1 = (q1 * c - q2 * s) * 0.125f;
    float rq2 = (q2 * c + q1 * s) * 0.125f;
    float k1 = K[base + d], k2 = K[base + d + 32];
    float rk1 = k1 * c - k2 * s;
    float rk2 = k2 * c + k1 * s;

    size_t ob = ((size_t)bh * L_ + l) * AD3;
    __nv_bfloat16 h1 = __float2bfloat16(rq1);
    __nv_bfloat16 l1 = __float2bfloat16(rq1 - __bfloat162float(h1));
    __nv_bfloat16 h2 = __float2bfloat16(rq2);
    __nv_bfloat16 l2 = __float2bfloat16(rq2 - __bfloat162float(h2));
    Q3[ob + 3*d + 0] = h1; Q3[ob + 3*d + 1] = h1; Q3[ob + 3*d + 2] = l1;
    Q3[ob + 3*(d+32) + 0] = h2; Q3[ob + 3*(d+32) + 1] = h2; Q3[ob + 3*(d+32) + 2] = l2;

    h1 = __float2bfloat16(rk1);
    l1 = __float2bfloat16(rk1 - __bfloat162float(h1));
    h2 = __float2bfloat16(rk2);
    l2 = __float2bfloat16(rk2 - __bfloat162float(h2));
    K3[ob + 3*d + 0] = h1; K3[ob + 3*d + 1] = l1; K3[ob + 3*d + 2] = h1;
    K3[ob + 3*(d+32) + 0] = h2; K3[ob + 3*(d+32) + 1] = l2; K3[ob + 3*(d+32) + 2] = h2;
}

// ---------------- V transpose + hi/lo split --------------------------------
// g_V [bl][h*64+d] fp32  ->  VTh/VTl [bh][d][l] bf16
__global__ __launch_bounds__(256) void vsplit_kernel(
    const float* __restrict__ V,
    __nv_bfloat16* __restrict__ VTh, __nv_bfloat16* __restrict__ VTl)
{
    __shared__ float tile[64][65];
    const int bh = blockIdx.y;
    const int b = bh >> 4, h = bh & 15;
    const int l0 = blockIdx.x * 64;
    const int tid = threadIdx.x;

#pragma unroll
    for (int r = 0; r < 4; r++) {
        int i = tid + r * 256;          // [0,1024): 64 rows x 16 float4
        int row = i >> 4, c4 = (i & 15) << 2;
        float4 v = *(const float4*)&V[((size_t)(b * L_ + l0 + row)) * D_ + h * HD_ + c4];
        tile[row][c4] = v.x; tile[row][c4+1] = v.y; tile[row][c4+2] = v.z; tile[row][c4+3] = v.w;
    }
    __syncthreads();

    const int d = tid >> 2, seg = tid & 3;   // 16 l per thread
    __align__(16) __nv_bfloat16 oh[16], ol[16];
#pragma unroll
    for (int j = 0; j < 16; j++) {
        float x = tile[seg * 16 + j][d];
        __nv_bfloat16 hi = __float2bfloat16(x);
        oh[j] = hi;
        ol[j] = __float2bfloat16(x - __bfloat162float(hi));
    }
    size_t off = ((size_t)bh * HD_ + d) * L_ + l0 + seg * 16;
    *(uint4*)&VTh[off] = ((uint4*)oh)[0]; *(uint4*)&VTh[off + 8] = ((uint4*)oh)[1];
    *(uint4*)&VTl[off] = ((uint4*)ol)[0]; *(uint4*)&VTl[off + 8] = ((uint4*)ol)[1];
}

// ---------------- fused flash attention on mma.sync ------------------------
// Block: 256 threads (8 warps x 16 q-rows = 128 q). K-tiles of 64 keys.
#define QROW 200   // 192 + 8 pad halves
#define VROW 72    // 64 + 8 pad halves
#define SQ3_OFF 0
#define SK3_OFF (128 * QROW * 2)                  // 51200
#define SVH_OFF (SK3_OFF + 64 * QROW * 2)         // 76800
#define SVL_OFF (SVH_OFF + 64 * VROW * 2)         // 86016
#define ATT_SMEM (SVL_OFF + 64 * VROW * 2)        // 95232

__global__ __launch_bounds__(256, 1) void fattn_kernel(
    const __nv_bfloat16* __restrict__ Q3, const __nv_bfloat16* __restrict__ K3,
    const __nv_bfloat16* __restrict__ VTh, const __nv_bfloat16* __restrict__ VTl,
    float* __restrict__ O)
{
    extern __shared__ char sm[];
    __nv_bfloat16* sQ = (__nv_bfloat16*)(sm + SQ3_OFF);
    __nv_bfloat16* sK = (__nv_bfloat16*)(sm + SK3_OFF);
    __nv_bfloat16* sVh = (__nv_bfloat16*)(sm + SVH_OFF);
    __nv_bfloat16* sVl = (__nv_bfloat16*)(sm + SVL_OFF);

    const int tid = threadIdx.x;
    const int wid = tid >> 5;
    const int lane = tid & 31;
    const int bh = blockIdx.y;
    const int b = bh >> 4, h = bh & 15;
    const int q0 = blockIdx.x * 128;
    const int wq = wid * 16;

    // stage Q3 tile [128][192]: 3072 uint4, 12 per thread
    {
        const __nv_bfloat16* src = Q3 + ((size_t)bh * L_ + q0) * AD3;
#pragma unroll
        for (int r = 0; r < 12; r++) {
            int i = tid + r * 256;
            int row = i / 24, c = i % 24;
            *(uint4*)&sQ[row * QROW + c * 8] = *(const uint4*)&src[(size_t)row * AD3 + c * 8];
        }
    }
    __syncthreads();

    // preload Q A-fragments: 12 k-frags
    uint32_t qf[12][4];
    {
        const uint32_t qb = smem_u32(sQ);
        const int lrow = wq + (lane & 15);
        const int koff = (lane >> 4) << 3;
#pragma unroll
        for (int kf = 0; kf < 12; kf++)
            ldm_x4(qf[kf], qb + (uint32_t)(lrow * QROW + kf * 16 + koff) * 2);
    }

    float oacc[8][4];
#pragma unroll
    for (int j = 0; j < 8; j++)
#pragma unroll
        for (int e = 0; e < 4; e++) oacc[j][e] = 0.f;
    float m0 = -1e30f, m1 = -1e30f, ls0 = 0.f, ls1 = 0.f;

    const uint32_t kb = smem_u32(sK);
    const uint32_t vhb = smem_u32(sVh);
    const uint32_t vlb = smem_u32(sVl);
    const int lrowB = (lane & 7) + ((lane >> 4) << 3);
    const int koffB = ((lane >> 3) & 1) << 3;

    for (int kt = 0; kt < L_ / 64; kt++) {
        __syncthreads();
        // stage K3 tile [64][192]: 1536 uint4 (6/thr); V tiles [64][64]: 512 uint4 (2/thr each)
        {
            const __nv_bfloat16* src = K3 + ((size_t)bh * L_ + kt * 64) * AD3;
#pragma unroll
            for (int r = 0; r < 6; r++) {
                int i = tid + r * 256;
                int row = i / 24, c = i % 24;
                *(uint4*)&sK[row * QROW + c * 8] = *(const uint4*)&src[(size_t)row * AD3 + c * 8];
            }
            const __nv_bfloat16* sh = VTh + (size_t)bh * HD_ * L_ + kt * 64;
            const __nv_bfloat16* sl = VTl + (size_t)bh * HD_ * L_ + kt * 64;
#pragma unroll
            for (int r = 0; r < 2; r++) {
                int i = tid + r * 256;
                int row = i >> 3, c = i & 7;
                *(uint4*)&sVh[row * VROW + c * 8] = *(const uint4*)&sh[(size_t)row * L_ + c * 8];
                *(uint4*)&sVl[row * VROW + c * 8] = *(const uint4*)&sl[(size_t)row * L_ + c * 8];
            }
        }
        __syncthreads();

        // S = Q3 K3^T (scores pre-scaled via Q)
        float sc[8][4];
#pragma unroll
        for (int j = 0; j < 8; j++)
#pragma unroll
            for (int e = 0; e < 4; e++) sc[j][e] = 0.f;
#pragma unroll
        for (int nj2 = 0; nj2 < 4; nj2++) {
#pragma unroll
            for (int kf = 0; kf < 12; kf++) {
                uint32_t bfr[4];
                ldm_x4(bfr, kb + (uint32_t)((nj2 * 16 + lrowB) * QROW + kf * 16 + koffB) * 2);
                mma_bf16(sc[nj2 * 2],     qf[kf], &bfr[0]);
                mma_bf16(sc[nj2 * 2 + 1], qf[kf], &bfr[2]);
            }
        }

        // online softmax (rows g and g+8; values replicated across 4-lane groups)
        float ml0 = -1e30f, ml1 = -1e30f;
#pragma unroll
        for (int j = 0; j < 8; j++) {
            ml0 = fmaxf(ml0, fmaxf(sc[j][0], sc[j][1]));
            ml1 = fmaxf(ml1, fmaxf(sc[j][2], sc[j][3]));
        }
        ml0 = fmaxf(ml0, __shfl_xor_sync(0xffffffffu, ml0, 1));
        ml0 = fmaxf(ml0, __shfl_xor_sync(0xffffffffu, ml0, 2));
        ml1 = fmaxf(ml1, __shfl_xor_sync(0xffffffffu, ml1, 1));
        ml1 = fmaxf(ml1, __shfl_xor_sync(0xffffffffu, ml1, 2));
        float mn0 = fmaxf(m0, ml0), mn1 = fmaxf(m1, ml1);
        float cr0 = __expf(m0 - mn0), cr1 = __expf(m1 - mn1);
        m0 = mn0; m1 = mn1;
        ls0 *= cr0; ls1 *= cr1;
#pragma unroll
        for (int j = 0; j < 8; j++) {
            oacc[j][0] *= cr0; oacc[j][1] *= cr0;
            oacc[j][2] *= cr1; oacc[j][3] *= cr1;
        }
        // exponentiate + pack P (hi & lo) directly as mma A-fragments
        uint32_t ph[4][4], pl[4][4];
#pragma unroll
        for (int kk = 0; kk < 4; kk++) {
            const int j0 = 2 * kk, j1 = 2 * kk + 1;
            float p00 = __expf(sc[j0][0] - m0), p01 = __expf(sc[j0][1] - m0);
            float p02 = __expf(sc[j0][2] - m1), p03 = __expf(sc[j0][3] - m1);
            float p10 = __expf(sc[j1][0] - m0), p11 = __expf(sc[j1][1] - m0);
            float p12 = __expf(sc[j1][2] - m1), p13 = __expf(sc[j1][3] - m1);
            ls0 += p00 + p01 + p10 + p11;
            ls1 += p02 + p03 + p12 + p13;
            ph[kk][0] = pack_bf2(p00, p01); pl[kk][0] = pack_bf2_lo(p00, p01, ph[kk][0]);
            ph[kk][1] = pack_bf2(p02, p03); pl[kk][1] = pack_bf2_lo(p02, p03, ph[kk][1]);
            ph[kk][2] = pack_bf2(p10, p11); pl[kk][2] = pack_bf2_lo(p10, p11, ph[kk][2]);
            ph[kk][3] = pack_bf2(p12, p13); pl[kk][3] = pack_bf2_lo(p12, p13, ph[kk][3]);
        }

        // O += P_hi*V_hi + P_hi*V_lo + P_lo*V_hi
#pragma unroll
        for (int nj2 = 0; nj2 < 4; nj2++) {
#pragma unroll
            for (int kk = 0; kk < 4; kk++) {
                uint32_t bh_[4], bl_[4];
                ldm_x4(bh_, vhb + (uint32_t)((nj2 * 16 + lrowB) * VROW + kk * 16 + koffB) * 2);
                ldm_x4(bl_, vlb + (uint32_t)((nj2 * 16 + lrowB) * VROW + kk * 16 + koffB) * 2);
                mma_bf16(oacc[nj2 * 2],     ph[kk], &bh_[0]);
                mma_bf16(oacc[nj2 * 2 + 1], ph[kk], &bh_[2]);
                mma_bf16(oacc[nj2 * 2],     ph[kk], &bl_[0]);
                mma_bf16(oacc[nj2 * 2 + 1], ph[kk], &bl_[2]);
                mma_bf16(oacc[nj2 * 2],     pl[kk], &bh_[0]);
                mma_bf16(oacc[nj2 * 2 + 1], pl[kk], &bh_[2]);
            }
        }
    }

    // finalize: reduce lsum across the 4-lane group, normalize, store
    ls0 += __shfl_xor_sync(0xffffffffu, ls0, 1);
    ls0 += __shfl_xor_sync(0xffffffffu, ls0, 2);
    ls1 += __shfl_xor_sync(0xffffffffu, ls1, 1);
    ls1 += __shfl_xor_sync(0xffffffffu, ls1, 2);
    const float inv0 = 1.f / ls0, inv1 = 1.f / ls1;
    const int g = lane >> 2;
    const int l0r = q0 + wq + g;
#pragma unroll
    for (int j = 0; j < 8; j++) {
        const int d0 = j * 8 + (lane & 3) * 2;
        size_t off0 = ((size_t)(b * L_ + l0r)) * D_ + h * HD_ + d0;
        size_t off1 = ((size_t)(b * L_ + l0r + 8)) * D_ + h * HD_ + d0;
        float2 v0 = {oacc[j][0] * inv0, oacc[j][1] * inv0};
        float2 v1 = {oacc[j][2] * inv1, oacc[j][3] * inv1};
        *(float2*)&O[off0] = v0;
        *(float2*)&O[off1] = v1;
    }
}

// ---------------- launch ---------------------------------------------------
extern "C" void kernel_launch(void* const* d_in, const int* in_sizes, int n_in,
                              void* d_out, int out_size)
{
    (void)in_sizes; (void)n_in; (void)out_size;
    const float* q  = (const float*)d_in[0];
    const float* k  = (const float*)d_in[1];
    const float* v  = (const float*)d_in[2];
    const float* fr = (const float*)d_in[3];
    const float* Wq = (const float*)d_in[4];
    const float* bq = (const float*)d_in[5];
    const float* Wk = (const float*)d_in[6];
    const float* bk = (const float*)d_in[7];
    const float* Wv = (const float*)d_in[8];
    const float* bv = (const float*)d_in[9];
    const float* Wo = (const float*)d_in[10];
    const float* bo = (const float*)d_in[11];
    float* out = (float*)d_out;

    float *Qs, *Ks, *Vs, *Os;
    __nv_bfloat16 *X3, *W3, *Q3, *K3, *VTh, *VTl;
    cudaGetSymbolAddress((void**)&Qs, g_Q);
    cudaGetSymbolAddress((void**)&Ks, g_K);
    cudaGetSymbolAddress((void**)&Vs, g_V);
    cudaGetSymbolAddress((void**)&Os, g_O);
    cudaGetSymbolAddress((void**)&X3, g_X3);
    cudaGetSymbolAddress((void**)&W3, g_W3);
    cudaGetSymbolAddress((void**)&Q3, g_Q3);
    cudaGetSymbolAddress((void**)&K3, g_K3);
    cudaGetSymbolAddress((void**)&VTh, g_VTh);
    cudaGetSymbolAddress((void**)&VTl, g_VTl);

    static int smem_set = 0;
    if (!smem_set) {
        cudaFuncSetAttribute(fattn_kernel,
                             cudaFuncAttributeMaxDynamicSharedMemorySize, ATT_SMEM);
        smem_set = 1;
    }

    const int xt8 = BL_ * D_ / 8;
    const int wt8 = D_ * D_ / 8;
    dim3 ggrid(D_ / BNt, BL_ / BMt);   // (8, 32)

    conv3_kernel<<<(xt8 + 255) / 256, 256>>>(q, X3, xt8, 0);
    conv3_kernel<<<(wt8 + 255) / 256, 256>>>(Wq, W3, wt8, 1);
    gemm_mma_kernel<<<ggrid, 256>>>(X3, W3, bq, Qs, D_);

    conv3_kernel<<<(xt8 + 255) / 256, 256>>>(k, X3, xt8, 0);
    conv3_kernel<<<(wt8 + 255) / 256, 256>>>(Wk, W3, wt8, 1);
    gemm_mma_kernel<<<ggrid, 256>>>(X3, W3, bk, Ks, D_);

    conv3_kernel<<<(xt8 + 255) / 256, 256>>>(v, X3, xt8, 0);
    conv3_kernel<<<(wt8 + 255) / 256, 256>>>(Wv, W3, wt8, 1);
    gemm_mma_kernel<<<ggrid, 256>>>(X3, W3, bv, Vs, D_);

    const int rs_total = BL_ * H_ * 32;
    rope_split_kernel<<<(rs_total + 255) / 256, 256>>>(Qs, Ks, fr, Q3, K3);
    vsplit_kernel<<<dim3(L_ / 64, BH_), 256>>>(Vs, VTh, VTl);

    fattn_kernel<<<dim3(L_ / 128, BH_), 256, ATT_SMEM>>>(Q3, K3, VTh, VTl, Os);

    conv3_kernel<<<(xt8 + 255) / 256, 256>>>(Os, X3, xt8, 0);
    conv3_kernel<<<(wt8 + 255) / 256, 256>>>(Wo, W3, wt8, 1);
    gemm_mma_kernel<<<ggrid, 256>>>(X3, W3, bo, out, D_);
}

// round 7
// speedup vs baseline: 7.2004x; 1.1448x over previous
#include <cuda_runtime.h>
#include <cuda_bf16.h>
#include <cstdint>

// Problem constants
#define D_   1024
#define H_   16
#define HD_  64
#define B_   2
#define L_   2048
#define BL_  (B_ * L_)   // 4096
#define K3_  (3 * D_)    // 3072 (K-tripled split-bf16 for projections)
#define BH_  (B_ * H_)   // 32
#define AD3  192         // tripled head dim

// ---------------- scratch (no allocations allowed -> __device__ globals) ----
__device__ float g_Q[(size_t)BL_ * D_];
__device__ float g_K[(size_t)BL_ * D_];
__device__ float g_V[(size_t)BL_ * D_];
__device__ float g_O[(size_t)BL_ * D_];
__device__ __nv_bfloat16 g_X3q[(size_t)BL_ * K3_];
__device__ __nv_bfloat16 g_X3k[(size_t)BL_ * K3_];
__device__ __nv_bfloat16 g_X3v[(size_t)BL_ * K3_];
__device__ __nv_bfloat16 g_W3q[(size_t)D_ * K3_];
__device__ __nv_bfloat16 g_W3k[(size_t)D_ * K3_];
__device__ __nv_bfloat16 g_W3v[(size_t)D_ * K3_];
__device__ __nv_bfloat16 g_W3o[(size_t)D_ * K3_];
__device__ __nv_bfloat16 g_Q3[(size_t)BH_ * L_ * AD3];
__device__ __nv_bfloat16 g_K3[(size_t)BH_ * L_ * AD3];
__device__ __nv_bfloat16 g_VTh[(size_t)BH_ * HD_ * L_];
__device__ __nv_bfloat16 g_VTl[(size_t)BH_ * HD_ * L_];

// ---------------- PTX helpers (sm_80-era ops: safe on plain sm_103) --------
__device__ __forceinline__ uint32_t smem_u32(const void* p) {
    uint32_t a;
    asm("{ .reg .u64 t; cvta.to.shared.u64 t, %1; cvt.u32.u64 %0, t; }"
        : "=r"(a) : "l"(p));
    return a;
}
__device__ __forceinline__ void ldm_x4(uint32_t* r, uint32_t addr) {
    asm volatile("ldmatrix.sync.aligned.m8n8.x4.shared.b16 {%0,%1,%2,%3}, [%4];"
                 : "=r"(r[0]), "=r"(r[1]), "=r"(r[2]), "=r"(r[3]) : "r"(addr));
}
__device__ __forceinline__ void mma_bf16(float* c, const uint32_t* a, const uint32_t* b) {
    asm volatile("mma.sync.aligned.m16n8k16.row.col.f32.bf16.bf16.f32 "
                 "{%0,%1,%2,%3}, {%4,%5,%6,%7}, {%8,%9}, {%0,%1,%2,%3};"
                 : "+f"(c[0]), "+f"(c[1]), "+f"(c[2]), "+f"(c[3])
                 : "r"(a[0]), "r"(a[1]), "r"(a[2]), "r"(a[3]), "r"(b[0]), "r"(b[1]));
}
__device__ __forceinline__ void cp16(uint32_t s, const void* g) {
    asm volatile("cp.async.cg.shared.global [%0], [%1], 16;" :: "r"(s), "l"(g));
}
#define CP_COMMIT() asm volatile("cp.async.commit_group;" ::: "memory")
#define CP_WAIT(n)  asm volatile("cp.async.wait_group %0;" :: "n"(n) : "memory")

__device__ __forceinline__ uint32_t pack_bf2(float x, float y) {
    __nv_bfloat162 t = __float22bfloat162_rn(make_float2(x, y));
    return *(uint32_t*)&t;
}
__device__ __forceinline__ uint32_t pack_bf2_lo(float x, float y, uint32_t hp) {
    __nv_bfloat162 h = *(__nv_bfloat162*)&hp;
    return pack_bf2(x - __bfloat162float(h.x), y - __bfloat162float(h.y));
}

// ---------------- split-bf16 K-tripling conversions ------------------------
__device__ __forceinline__ void conv3_body(
    const float* __restrict__ in, __nv_bfloat16* __restrict__ out, int total8, int mode)
{
    int idx = blockIdx.x * blockDim.x + threadIdx.x;
    if (idx >= total8) return;
    float4 v0 = ((const float4*)in)[idx * 2];
    float4 v1 = ((const float4*)in)[idx * 2 + 1];
    float a[8] = {v0.x, v0.y, v0.z, v0.w, v1.x, v1.y, v1.z, v1.w};
    __align__(16) __nv_bfloat16 o[24];
#pragma unroll
    for (int i = 0; i < 8; i++) {
        __nv_bfloat16 hi = __float2bfloat16(a[i]);
        __nv_bfloat16 lo = __float2bfloat16(a[i] - __bfloat162float(hi));
        if (mode == 0) { o[3*i] = hi; o[3*i+1] = hi; o[3*i+2] = lo; }
        else           { o[3*i] = hi; o[3*i+1] = lo; o[3*i+2] = hi; }
    }
    uint4* dst = (uint4*)(out + (size_t)idx * 24);
    const uint4* src = (const uint4*)o;
    dst[0] = src[0]; dst[1] = src[1]; dst[2] = src[2];
}

// single-tensor (for O activation)
__global__ __launch_bounds__(256) void conv3_kernel(
    const float* __restrict__ in, __nv_bfloat16* __restrict__ out, int total8, int mode)
{
    conv3_body(in, out, total8, mode);
}
// batched activations q,k,v (z selects)
__global__ __launch_bounds__(256) void conv3x_kernel(
    const float* __restrict__ a0, const float* __restrict__ a1, const float* __restrict__ a2,
    __nv_bfloat16* __restrict__ o0, __nv_bfloat16* __restrict__ o1, __nv_bfloat16* __restrict__ o2,
    int total8)
{
    const int z = blockIdx.z;
    const float* in = (z == 0) ? a0 : (z == 1) ? a1 : a2;
    __nv_bfloat16* out = (z == 0) ? o0 : (z == 1) ? o1 : o2;
    conv3_body(in, out, total8, 0);
}
// batched weights Wq,Wk,Wv,Wo (z selects)
__global__ __launch_bounds__(256) void conv3w_kernel(
    const float* __restrict__ a0, const float* __restrict__ a1,
    const float* __restrict__ a2, const float* __restrict__ a3,
    __nv_bfloat16* __restrict__ o0, __nv_bfloat16* __restrict__ o1,
    __nv_bfloat16* __restrict__ o2, __nv_bfloat16* __restrict__ o3,
    int total8)
{
    const int z = blockIdx.z;
    const float* in = (z == 0) ? a0 : (z == 1) ? a1 : (z == 2) ? a2 : a3;
    __nv_bfloat16* out = (z == 0) ? o0 : (z == 1) ? o1 : (z == 2) ? o2 : o3;
    conv3_body(in, out, total8, 1);
}

// ---------------- mma.sync GEMM, cp.async 2-stage, batched via grid.z ------
#define BMt 128
#define BNt 128
#define KS  32
#define AROW 40
#define NCH (K3_ / KS)          // 96

__global__ __launch_bounds__(256) void gemm_mma_kernel(
    const __nv_bfloat16* __restrict__ A0, const __nv_bfloat16* __restrict__ A1,
    const __nv_bfloat16* __restrict__ A2,
    const __nv_bfloat16* __restrict__ W0, const __nv_bfloat16* __restrict__ W1,
    const __nv_bfloat16* __restrict__ W2,
    const float* __restrict__ b0_, const float* __restrict__ b1_,
    const float* __restrict__ b2_,
    float* __restrict__ C0, float* __restrict__ C1, float* __restrict__ C2,
    int N)
{
    __shared__ __align__(16) __nv_bfloat16 As[2][BMt][AROW];
    __shared__ __align__(16) __nv_bfloat16 Bs[2][BNt][AROW];

    const int z = blockIdx.z;
    const __nv_bfloat16* A3 = (z == 0) ? A0 : (z == 1) ? A1 : A2;
    const __nv_bfloat16* W3 = (z == 0) ? W0 : (z == 1) ? W1 : W2;
    const float* bias = (z == 0) ? b0_ : (z == 1) ? b1_ : b2_;
    float* C = (z == 0) ? C0 : (z == 1) ? C1 : C2;

    const int tid  = threadIdx.x;
    const int wid  = tid >> 5;
    const int lane = tid & 31;
    const int bm = blockIdx.y * BMt;
    const int bn = blockIdx.x * BNt;
    const int wm = (wid >> 2) * 64;
    const int wn = (wid & 3) * 32;

    const int r0row = tid >> 2,         r0c = tid & 3;
    const int r1row = (tid + 256) >> 2, r1c = (tid + 256) & 3;
    const uint32_t as0 = smem_u32(&As[0][0][0]);
    const uint32_t bs0 = smem_u32(&Bs[0][0][0]);
    const uint32_t abytes = BMt * AROW * 2;   // one A buffer

    float acc[4][4][4];
#pragma unroll
    for (int mi = 0; mi < 4; mi++)
#pragma unroll
        for (int nj = 0; nj < 4; nj++)
#pragma unroll
            for (int e = 0; e < 4; e++) acc[mi][nj][e] = 0.f;

    // prologue: chunk 0 -> buf 0
    cp16(as0 + (uint32_t)(r0row * AROW + r0c * 8) * 2, &A3[(size_t)(bm + r0row) * K3_ + r0c * 8]);
    cp16(as0 + (uint32_t)(r1row * AROW + r1c * 8) * 2, &A3[(size_t)(bm + r1row) * K3_ + r1c * 8]);
    cp16(bs0 + (uint32_t)(r0row * AROW + r0c * 8) * 2, &W3[(size_t)(bn + r0row) * K3_ + r0c * 8]);
    cp16(bs0 + (uint32_t)(r1row * AROW + r1c * 8) * 2, &W3[(size_t)(bn + r1row) * K3_ + r1c * 8]);
    CP_COMMIT();
    CP_WAIT(0);
    __syncthreads();

    const int lrowA = wm + (lane & 15);
    const int koffA = (lane >> 4) << 3;
    const int lrowB = wn + (lane & 7) + ((lane >> 4) << 3);
    const int koffB = ((lane >> 3) & 1) << 3;

    for (int ch = 0; ch < NCH; ch++) {
        const int p = ch & 1;
        if (ch + 1 < NCH) {
            const int k0 = (ch + 1) * KS;
            const uint32_t aq = as0 + (p ^ 1) * abytes;
            const uint32_t bq = bs0 + (p ^ 1) * abytes;
            cp16(aq + (uint32_t)(r0row * AROW + r0c * 8) * 2, &A3[(size_t)(bm + r0row) * K3_ + k0 + r0c * 8]);
            cp16(aq + (uint32_t)(r1row * AROW + r1c * 8) * 2, &A3[(size_t)(bm + r1row) * K3_ + k0 + r1c * 8]);
            cp16(bq + (uint32_t)(r0row * AROW + r0c * 8) * 2, &W3[(size_t)(bn + r0row) * K3_ + k0 + r0c * 8]);
            cp16(bq + (uint32_t)(r1row * AROW + r1c * 8) * 2, &W3[(size_t)(bn + r1row) * K3_ + k0 + r1c * 8]);
        }
        CP_COMMIT();

        const uint32_t a_base = as0 + p * abytes;
        const uint32_t b_base = bs0 + p * abytes;
#pragma unroll
        for (int kk = 0; kk < 2; kk++) {
            uint32_t afr[4][4], bfr[2][4];
#pragma unroll
            for (int mi = 0; mi < 4; mi++)
                ldm_x4(afr[mi], a_base + (uint32_t)(((lrowA + mi * 16) * AROW) + kk * 16 + koffA) * 2);
#pragma unroll
            for (int nj2 = 0; nj2 < 2; nj2++)
                ldm_x4(bfr[nj2], b_base + (uint32_t)(((lrowB + nj2 * 16) * AROW) + kk * 16 + koffB) * 2);
#pragma unroll
            for (int mi = 0; mi < 4; mi++)
#pragma unroll
                for (int nj = 0; nj < 4; nj++)
                    mma_bf16(acc[mi][nj], afr[mi], &bfr[nj >> 1][(nj & 1) * 2]);
        }
        CP_WAIT(0);
        __syncthreads();
    }

    const int crow = wm + (lane >> 2);
    const int ccol = wn + (lane & 3) * 2;
#pragma unroll
    for (int mi = 0; mi < 4; mi++) {
#pragma unroll
        for (int nj = 0; nj < 4; nj++) {
            const int m0 = bm + crow + mi * 16;
            const int n0 = bn + ccol + nj * 8;
            const float b0v = __ldg(&bias[n0]), b1v = __ldg(&bias[n0 + 1]);
            float2 v0 = {acc[mi][nj][0] + b0v, acc[mi][nj][1] + b1v};
            float2 v1 = {acc[mi][nj][2] + b0v, acc[mi][nj][3] + b1v};
            *(float2*)&C[(size_t)m0 * N + n0]       = v0;
            *(float2*)&C[(size_t)(m0 + 8) * N + n0] = v1;
        }
    }
}

// ---------------- RoPE + triple-split into per-head layout -----------------
__global__ __launch_bounds__(256) void rope_split_kernel(
    const float* __restrict__ Q, const float* __restrict__ K,
    const float* __restrict__ freqs,
    __nv_bfloat16* __restrict__ Q3, __nv_bfloat16* __restrict__ K3)
{
    int idx = blockIdx.x * blockDim.x + threadIdx.x;
    int d  = idx & 31;
    int h  = (idx >> 5) & 15;
    int bl = idx >> 9;
    if (bl >= BL_) return;
    int l = bl & (L_ - 1);
    int b = bl >> 11;
    int bh = b * H_ + h;

    float f = freqs[l * HD_ + d];
    float s, c;
    sincosf(f, &s, &c);

    size_t base = (size_t)bl * D_ + h * HD_;
    float q1 = Q[base + d], q2 = Q[base + d + 32];
    float rq1 = (q1 * c - q2 * s) * 0.125f;
    float rq2 = (q2 * c + q1 * s) * 0.125f;
    float k1 = K[base + d], k2 = K[base + d + 32];
    float rk1 = k1 * c - k2 * s;
    float rk2 = k2 * c + k1 * s;

    size_t ob = ((size_t)bh * L_ + l) * AD3;
    __nv_bfloat16 h1 = __float2bfloat16(rq1);
    __nv_bfloat16 l1 = __float2bfloat16(rq1 - __bfloat162float(h1));
    __nv_bfloat16 h2 = __float2bfloat16(rq2);
    __nv_bfloat16 l2 = __float2bfloat16(rq2 - __bfloat162float(h2));
    Q3[ob + 3*d + 0] = h1; Q3[ob + 3*d + 1] = h1; Q3[ob + 3*d + 2] = l1;
    Q3[ob + 3*(d+32) + 0] = h2; Q3[ob + 3*(d+32) + 1] = h2; Q3[ob + 3*(d+32) + 2] = l2;

    h1 = __float2bfloat16(rk1);
    l1 = __float2bfloat16(rk1 - __bfloat162float(h1));
    h2 = __float2bfloat16(rk2);
    l2 = __float2bfloat16(rk2 - __bfloat162float(h2));
    K3[ob + 3*d + 0] = h1; K3[ob + 3*d + 1] = l1; K3[ob + 3*d + 2] = h1;
    K3[ob + 3*(d+32) + 0] = h2; K3[ob + 3*(d+32) + 1] = l2; K3[ob + 3*(d+32) + 2] = h2;
}

// ---------------- V transpose + hi/lo split --------------------------------
__global__ __launch_bounds__(256) void vsplit_kernel(
    const float* __restrict__ V,
    __nv_bfloat16* __restrict__ VTh, __nv_bfloat16* __restrict__ VTl)
{
    __shared__ float tile[64][65];
    const int bh = blockIdx.y;
    const int b = bh >> 4, h = bh & 15;
    const int l0 = blockIdx.x * 64;
    const int tid = threadIdx.x;

#pragma unroll
    for (int r = 0; r < 4; r++) {
        int i = tid + r * 256;
        int row = i >> 4, c4 = (i & 15) << 2;
        float4 v = *(const float4*)&V[((size_t)(b * L_ + l0 + row)) * D_ + h * HD_ + c4];
        tile[row][c4] = v.x; tile[row][c4+1] = v.y; tile[row][c4+2] = v.z; tile[row][c4+3] = v.w;
    }
    __syncthreads();

    const int d = tid >> 2, seg = tid & 3;
    __align__(16) __nv_bfloat16 oh[16], ol[16];
#pragma unroll
    for (int j = 0; j < 16; j++) {
        float x = tile[seg * 16 + j][d];
        __nv_bfloat16 hi = __float2bfloat16(x);
        oh[j] = hi;
        ol[j] = __float2bfloat16(x - __bfloat162float(hi));
    }
    size_t off = ((size_t)bh * HD_ + d) * L_ + l0 + seg * 16;
    *(uint4*)&VTh[off] = ((uint4*)oh)[0]; *(uint4*)&VTh[off + 8] = ((uint4*)oh)[1];
    *(uint4*)&VTl[off] = ((uint4*)ol)[0]; *(uint4*)&VTl[off + 8] = ((uint4*)ol)[1];
}

// ---------------- fused flash attention, cp.async double-buffered K/V ------
// smem (halves): [0, 25600) = Q tile, reused as buf1 after fragment load.
//                [25600, 47616) = buf0.  buffer = K(12800) | Vh(4608) | Vl(4608)
#define QROW 200
#define VROW 72
#define BUF_K 0
#define BUF_VH 12800
#define BUF_VL 17408
#define BUFH 22016
#define BUF0H 25600
#define ATT_SMEM ((BUF0H + BUFH) * 2)   // 95232 bytes
#define NT (L_ / 64)                    // 32

__device__ __forceinline__ void fattn_stage(
    uint32_t smb, uint32_t offh, int tid, int bh, int kt,
    const __nv_bfloat16* __restrict__ K3,
    const __nv_bfloat16* __restrict__ VTh, const __nv_bfloat16* __restrict__ VTl)
{
    const __nv_bfloat16* ks = K3 + ((size_t)bh * L_ + kt * 64) * AD3;
#pragma unroll
    for (int r = 0; r < 6; r++) {
        int i = tid + r * 256;
        int row = i / 24, c = i % 24;
        cp16(smb + (offh + BUF_K + row * QROW + c * 8) * 2, ks + (size_t)row * AD3 + c * 8);
    }
    const __nv_bfloat16* sh = VTh + (size_t)bh * HD_ * L_ + kt * 64;
    const __nv_bfloat16* sl = VTl + (size_t)bh * HD_ * L_ + kt * 64;
#pragma unroll
    for (int r = 0; r < 2; r++) {
        int i = tid + r * 256;
        int row = i >> 3, c = i & 7;
        cp16(smb + (offh + BUF_VH + row * VROW + c * 8) * 2, sh + (size_t)row * L_ + c * 8);
        cp16(smb + (offh + BUF_VL + row * VROW + c * 8) * 2, sl + (size_t)row * L_ + c * 8);
    }
}

__global__ __launch_bounds__(256, 1) void fattn_kernel(
    const __nv_bfloat16* __restrict__ Q3, const __nv_bfloat16* __restrict__ K3,
    const __nv_bfloat16* __restrict__ VTh, const __nv_bfloat16* __restrict__ VTl,
    float* __restrict__ O)
{
    extern __shared__ char sm[];
    __nv_bfloat16* sQ = (__nv_bfloat16*)sm;
    const uint32_t smb = smem_u32(sm);

    const int tid = threadIdx.x;
    const int wid = tid >> 5;
    const int lane = tid & 31;
    const int bh = blockIdx.y;
    const int b = bh >> 4, h = bh & 15;
    const int q0 = blockIdx.x * 128;
    const int wq = wid * 16;

    // issue tile0 -> buf0 first (doesn't touch Q region), then stage Q
    fattn_stage(smb, BUF0H, tid, bh, 0, K3, VTh, VTl);
    CP_COMMIT();
    {
        const __nv_bfloat16* src = Q3 + ((size_t)bh * L_ + q0) * AD3;
#pragma unroll
        for (int r = 0; r < 12; r++) {
            int i = tid + r * 256;
            int row = i / 24, c = i % 24;
            *(uint4*)&sQ[row * QROW + c * 8] = *(const uint4*)&src[(size_t)row * AD3 + c * 8];
        }
    }
    __syncthreads();

    uint32_t qf[12][4];
    {
        const int lrow = wq + (lane & 15);
        const int koff = (lane >> 4) << 3;
#pragma unroll
        for (int kf = 0; kf < 12; kf++)
            ldm_x4(qf[kf], smb + (uint32_t)(lrow * QROW + kf * 16 + koff) * 2);
    }
    __syncthreads();            // Q region free -> becomes buf1
    fattn_stage(smb, 0, tid, bh, 1, K3, VTh, VTl);
    CP_COMMIT();

    float oacc[8][4];
#pragma unroll
    for (int j = 0; j < 8; j++)
#pragma unroll
        for (int e = 0; e < 4; e++) oacc[j][e] = 0.f;
    float m0 = -1e30f, m1 = -1e30f, ls0 = 0.f, ls1 = 0.f;

    const int lrowB = (lane & 7) + ((lane >> 4) << 3);
    const int koffB = ((lane >> 3) & 1) << 3;

    for (int kt = 0; kt < NT; kt++) {
        const uint32_t offh = (kt & 1) ? 0u : (uint32_t)BUF0H;
        CP_WAIT(1);
        __syncthreads();

        const uint32_t kb  = smb + (offh + BUF_K) * 2;
        const uint32_t vhb = smb + (offh + BUF_VH) * 2;
        const uint32_t vlb = smb + (offh + BUF_VL) * 2;

        // S = Q3 K3^T (scores pre-scaled via Q)
        float sc[8][4];
#pragma unroll
        for (int j = 0; j < 8; j++)
#pragma unroll
            for (int e = 0; e < 4; e++) sc[j][e] = 0.f;
#pragma unroll
        for (int nj2 = 0; nj2 < 4; nj2++) {
#pragma unroll
            for (int kf = 0; kf < 12; kf++) {
                uint32_t bfr[4];
                ldm_x4(bfr, kb + (uint32_t)((nj2 * 16 + lrowB) * QROW + kf * 16 + koffB) * 2);
                mma_bf16(sc[nj2 * 2],     qf[kf], &bfr[0]);
                mma_bf16(sc[nj2 * 2 + 1], qf[kf], &bfr[2]);
            }
        }

        // online softmax
        float ml0 = -1e30f, ml1 = -1e30f;
#pragma unroll
        for (int j = 0; j < 8; j++) {
            ml0 = fmaxf(ml0, fmaxf(sc[j][0], sc[j][1]));
            ml1 = fmaxf(ml1, fmaxf(sc[j][2], sc[j][3]));
        }
        ml0 = fmaxf(ml0, __shfl_xor_sync(0xffffffffu, ml0, 1));
        ml0 = fmaxf(ml0, __shfl_xor_sync(0xffffffffu, ml0, 2));
        ml1 = fmaxf(ml1, __shfl_xor_sync(0xffffffffu, ml1, 1));
        ml1 = fmaxf(ml1, __shfl_xor_sync(0xffffffffu, ml1, 2));
        float mn0 = fmaxf(m0, ml0), mn1 = fmaxf(m1, ml1);
        float cr0 = __expf(m0 - mn0), cr1 = __expf(m1 - mn1);
        m0 = mn0; m1 = mn1;
        ls0 *= cr0; ls1 *= cr1;
#pragma unroll
        for (int j = 0; j < 8; j++) {
            oacc[j][0] *= cr0; oacc[j][1] *= cr0;
            oacc[j][2] *= cr1; oacc[j][3] *= cr1;
        }
        uint32_t ph[4][4], pl[4][4];
#pragma unroll
        for (int kk = 0; kk < 4; kk++) {
            const int j0 = 2 * kk, j1 = 2 * kk + 1;
            float p00 = __expf(sc[j0][0] - m0), p01 = __expf(sc[j0][1] - m0);
            float p02 = __expf(sc[j0][2] - m1), p03 = __expf(sc[j0][3] - m1);
            float p10 = __expf(sc[j1][0] - m0), p11 = __expf(sc[j1][1] - m0);
            float p12 = __expf(sc[j1][2] - m1), p13 = __expf(sc[j1][3] - m1);
            ls0 += p00 + p01 + p10 + p11;
            ls1 += p02 + p03 + p12 + p13;
            ph[kk][0] = pack_bf2(p00, p01); pl[kk][0] = pack_bf2_lo(p00, p01, ph[kk][0]);
            ph[kk][1] = pack_bf2(p02, p03); pl[kk][1] = pack_bf2_lo(p02, p03, ph[kk][1]);
            ph[kk][2] = pack_bf2(p10, p11); pl[kk][2] = pack_bf2_lo(p10, p11, ph[kk][2]);
            ph[kk][3] = pack_bf2(p12, p13); pl[kk][3] = pack_bf2_lo(p12, p13, ph[kk][3]);
        }

        // O += P_hi*V_hi + P_hi*V_lo + P_lo*V_hi
#pragma unroll
        for (int nj2 = 0; nj2 < 4; nj2++) {
#pragma unroll
            for (int kk = 0; kk < 4; kk++) {
                uint32_t bh_[4], bl_[4];
                ldm_x4(bh_, vhb + (uint32_t)((nj2 * 16 + lrowB) * VROW + kk * 16 + koffB) * 2);
                ldm_x4(bl_, vlb + (uint32_t)((nj2 * 16 + lrowB) * VROW + kk * 16 + koffB) * 2);
                mma_bf16(oacc[nj2 * 2],     ph[kk], &bh_[0]);
                mma_bf16(oacc[nj2 * 2 + 1], ph[kk], &bh_[2]);
                mma_bf16(oacc[nj2 * 2],     ph[kk], &bl_[0]);
                mma_bf16(oacc[nj2 * 2 + 1], ph[kk], &bl_[2]);
                mma_bf16(oacc[nj2 * 2],     pl[kk], &bh_[0]);
                mma_bf16(oacc[nj2 * 2 + 1], pl[kk], &bh_[2]);
            }
        }

        __syncthreads();   // all warps done reading buf before refill
        if (kt + 2 < NT)
            fattn_stage(smb, offh, tid, bh, kt + 2, K3, VTh, VTl);
        CP_COMMIT();       // empty group when nothing issued (keeps count aligned)
    }

    ls0 += __shfl_xor_sync(0xffffffffu, ls0, 1);
    ls0 += __shfl_xor_sync(0xffffffffu, ls0, 2);
    ls1 += __shfl_xor_sync(0xffffffffu, ls1, 1);
    ls1 += __shfl_xor_sync(0xffffffffu, ls1, 2);
    const float inv0 = 1.f / ls0, inv1 = 1.f / ls1;
    const int g = lane >> 2;
    const int l0r = q0 + wq + g;
#pragma unroll
    for (int j = 0; j < 8; j++) {
        const int d0 = j * 8 + (lane & 3) * 2;
        size_t off0 = ((size_t)(b * L_ + l0r)) * D_ + h * HD_ + d0;
        size_t off1 = ((size_t)(b * L_ + l0r + 8)) * D_ + h * HD_ + d0;
        float2 v0 = {oacc[j][0] * inv0, oacc[j][1] * inv0};
        float2 v1 = {oacc[j][2] * inv1, oacc[j][3] * inv1};
        *(float2*)&O[off0] = v0;
        *(float2*)&O[off1] = v1;
    }
}

// ---------------- launch ---------------------------------------------------
extern "C" void kernel_launch(void* const* d_in, const int* in_sizes, int n_in,
                              void* d_out, int out_size)
{
    (void)in_sizes; (void)n_in; (void)out_size;
    const float* q  = (const float*)d_in[0];
    const float* k  = (const float*)d_in[1];
    const float* v  = (const float*)d_in[2];
    const float* fr = (const float*)d_in[3];
    const float* Wq = (const float*)d_in[4];
    const float* bq = (const float*)d_in[5];
    const float* Wk = (const float*)d_in[6];
    const float* bk = (const float*)d_in[7];
    const float* Wv = (const float*)d_in[8];
    const float* bv = (const float*)d_in[9];
    const float* Wo = (const float*)d_in[10];
    const float* bo = (const float*)d_in[11];
    float* out = (float*)d_out;

    float *Qs, *Ks, *Vs, *Os;
    __nv_bfloat16 *X3q, *X3k, *X3v, *W3q, *W3k, *W3v, *W3o, *Q3, *K3, *VTh, *VTl;
    cudaGetSymbolAddress((void**)&Qs, g_Q);
    cudaGetSymbolAddress((void**)&Ks, g_K);
    cudaGetSymbolAddress((void**)&Vs, g_V);
    cudaGetSymbolAddress((void**)&Os, g_O);
    cudaGetSymbolAddress((void**)&X3q, g_X3q);
    cudaGetSymbolAddress((void**)&X3k, g_X3k);
    cudaGetSymbolAddress((void**)&X3v, g_X3v);
    cudaGetSymbolAddress((void**)&W3q, g_W3q);
    cudaGetSymbolAddress((void**)&W3k, g_W3k);
    cudaGetSymbolAddress((void**)&W3v, g_W3v);
    cudaGetSymbolAddress((void**)&W3o, g_W3o);
    cudaGetSymbolAddress((void**)&Q3, g_Q3);
    cudaGetSymbolAddress((void**)&K3, g_K3);
    cudaGetSymbolAddress((void**)&VTh, g_VTh);
    cudaGetSymbolAddress((void**)&VTl, g_VTl);

    cudaFuncSetAttribute(fattn_kernel,
                         cudaFuncAttributeMaxDynamicSharedMemorySize, ATT_SMEM);

    const int xt8 = BL_ * D_ / 8;
    const int wt8 = D_ * D_ / 8;
    const int xblocks = (xt8 + 255) / 256;
    const int wblocks = (wt8 + 255) / 256;

    // all 4 weight conversions up-front (one launch)
    conv3w_kernel<<<dim3(wblocks, 1, 4), 256>>>(Wq, Wk, Wv, Wo, W3q, W3k, W3v, W3o, wt8);
    // q, k, v activation conversions (one launch)
    conv3x_kernel<<<dim3(xblocks, 1, 3), 256>>>(q, k, v, X3q, X3k, X3v, xt8);
    // Q, K, V projections (one batched launch)
    gemm_mma_kernel<<<dim3(D_ / BNt, BL_ / BMt, 3), 256>>>(
        X3q, X3k, X3v, W3q, W3k, W3v, bq, bk, bv, Qs, Ks, Vs, D_);

    const int rs_total = BL_ * H_ * 32;
    rope_split_kernel<<<(rs_total + 255) / 256, 256>>>(Qs, Ks, fr, Q3, K3);
    vsplit_kernel<<<dim3(L_ / 64, BH_), 256>>>(Vs, VTh, VTl);

    fattn_kernel<<<dim3(L_ / 128, BH_), 256, ATT_SMEM>>>(Q3, K3, VTh, VTl, Os);

    conv3_kernel<<<xblocks, 256>>>(Os, X3q, xt8, 0);
    gemm_mma_kernel<<<dim3(D_ / BNt, BL_ / BMt, 1), 256>>>(
        X3q, X3q, X3q, W3o, W3o, W3o, bo, bo, bo, out, out, out, D_);
}